// round 17
// baseline (speedup 1.0000x reference)
#include <cuda_runtime.h>

// HONU degree-3: out[r] = sum_{a<=b<=c} w(a,b,c) * xs[a][r]*xs[b][r]*xs[c][r]
// xs[0][r]=1 (bias). Weight index = lexicographic rank (closed form); the
// comb_idx input is redundant and ignored.
//
// Pair factorization: s_ab[r] = sum_c w_abc * xs[c][r];
//                     out[r] += xs[a][r]*xs[b][r]*s_ab[r].
// FOUR 'a'-streams (same b) share each xs[c] LDS.128; warp owns all 256 rows
// (8 rows/thread), PLAIN float accumulators (no packed-f32x2 asm: the paired
// 64-bit asm operands are suspected of fragmenting register allocation ->
// the persistent regs=126 spills of R6-R16).
// Weights staged per-warp via cp.async with ZERO-FILL (srcsz=0) outside the
// warp's [k0,kend) window -> the inner chunk loop is straight-line 8x
// (1 wLDS.128 + 2 xLDS.128 + 32 FFMA), no masks, no tails. xs padded to 136
// zero feature rows absorbs k-overrun (weight there is 0).
// Grid=148 (1 wave), 512 thr. Transposed g_partial + parallel reduce kernel.

#define NFEAT 129
#define XROWS 136
#define NROW  256
#define NBLK  148
#define WPB   16
#define NRANGE (NBLK * WPB)   // 2368 ranges, one warp each (full 256 rows)

__host__ __device__ __forceinline__ int c2i(int v) { return v * (v - 1) / 2; }
__host__ __device__ __forceinline__ int c3i(int v) { return v * (v - 1) * (v - 2) / 6; }

// flat lexicographic rank of combo (a, b, b); total combos = C(131,3) = 366145
__device__ __forceinline__ int comb_base(int a, int b) {
    return 366145 - c3i(131 - a) + c2i(130 - a) - c2i(130 - b);
}

// total c-steps over all (b, quartet) rows: sum_b ceil((b+1)/4)*(129-b)
constexpr int t4_calc() {
    int t = 0;
    for (int b = 0; b < NFEAT; b++) t += ((b + 4) / 4) * (NFEAT - b);
    return t;
}
constexpr int T4 = t4_calc();

__device__ float g_partial[NROW * NBLK];   // transposed: [row][block]

__device__ __forceinline__ void cp_async4z(unsigned int daddr, const float* g,
                                           int srcsz) {
    // srcsz = 4 -> copy 4 bytes; srcsz = 0 -> write 4 bytes of ZERO
    asm volatile("cp.async.ca.shared.global [%0], [%1], 4, %2;\n"
                 :: "r"(daddr), "l"(g), "r"(srcsz));
}
__device__ __forceinline__ void cp_commit() {
    asm volatile("cp.async.commit_group;\n");
}
__device__ __forceinline__ void cp_wait1() {
    asm volatile("cp.async.wait_group 1;\n");
}
__device__ __forceinline__ void cp_wait0() {
    asm volatile("cp.async.wait_group 0;\n");
}

__global__ void __launch_bounds__(512, 1)
honu_main(const float* __restrict__ x, const float* __restrict__ w) {
    extern __shared__ float smem[];
    float* xs   = smem;                   // [136][256] feature-major (129+ zero)
    float* obuf = smem + XROWS * NROW;    // [16][256] per-warp partials
    float* wst  = obuf + WPB * NROW;      // [16][2][8][4] staged weights
    __shared__ int sP4[130];              // prefix of c-steps before feature b

    int tid = threadIdx.x;

    // ---- prefix table ----
    if (tid < 130) {
        int p = 0;
        for (int bb = 0; bb < tid && bb < NFEAT; bb++)
            p += ((bb + 4) / 4) * (NFEAT - bb);
        sP4[tid] = p;                     // sP4[129] == T4
    }

    // ---- x transposed into smem; pad rows 129..135 zeroed ----
    {
        int r = tid & 255, h = tid >> 8;
        const float4* xg = (const float4*)(x + (size_t)r * 128 + h * 64);
#pragma unroll
        for (int k = 0; k < 16; k++) {
            float4 v = xg[k];
            int f = h * 64 + 4 * k;
            xs[(f + 1) * NROW + r] = v.x;
            xs[(f + 2) * NROW + r] = v.y;
            xs[(f + 3) * NROW + r] = v.z;
            xs[(f + 4) * NROW + r] = v.w;
        }
        if (h == 0) {
            xs[r] = 1.0f;                 // bias feature
        } else {
#pragma unroll
            for (int f = NFEAT; f < XROWS; f++) xs[f * NROW + r] = 0.0f;
        }
    }
    __syncthreads();

    int warp = tid >> 5, lane = tid & 31;
    int range = blockIdx.x * WPB + warp;
    int st = lane & 3;                    // staging: stream this lane loads
    int u8 = lane >> 2;                   // staging: kstep within chunk (0..7)
    float* wsw = wst + warp * 64;         // two 32-float buffers per warp
    unsigned int wdst =
        (unsigned int)__cvta_generic_to_shared(wsw + u8 * 4 + st);

    int s = (int)(((long long)T4 * range) / NRANGE);
    int e = (int)(((long long)T4 * (range + 1)) / NRANGE);

    // ---- decode start -> (b, quartet o, kstep k0) via binary search ----
    int lo = 0, hi = NFEAT - 1;
    while (lo < hi) {                     // largest b with sP4[b] <= s
        int mid = (lo + hi + 1) >> 1;
        if (sP4[mid] <= s) lo = mid; else hi = mid - 1;
    }
    int b = lo;
    int rem = s - sP4[b];
    int L = NFEAT - b;
    int o = rem / L;
    int k0 = rem % L;
    int pos = s;

    float ov[8] = {0, 0, 0, 0, 0, 0, 0, 0};   // 8 rows of out partial
    const float4* xs4 = (const float4*)xs;    // 64 quads per feature

    while (pos < e) {
        L = NFEAT - b;
        int a0 = o << 2;
        int na = b + 1 - a0;
        if (na > 4) na = 4;
        int kend = k0 + (e - pos);
        if (kend > L) kend = L;

        int aj = (st < na) ? (a0 + st) : a0;   // dead streams alias stream 0
        const float* wlane = w + comb_base(aj, b);

        int cs0 = k0 >> 3, csE = (kend + 7) >> 3;

        // stage chunk cs0 (zero-fill outside [k0,kend))
        {
            int idx = (cs0 << 3) + u8;
            int ssz = (idx >= k0 && idx < kend) ? 4 : 0;
            int ic  = (idx < L) ? idx : (L - 1);
            cp_async4z(wdst + ((cs0 & 1) << 7), wlane + ic, ssz);
            cp_commit();
        }

        float acc[4][8];
#pragma unroll
        for (int j = 0; j < 4; j++)
#pragma unroll
            for (int q = 0; q < 8; q++) acc[j][q] = 0.0f;

        for (int cs = cs0; cs < csE; cs++) {
            if (cs + 1 < csE) {           // stage next chunk (zero-filled)
                int idx = ((cs + 1) << 3) + u8;
                int ssz = (idx < kend) ? 4 : 0;   // idx >= k0 holds for cs>cs0
                int ic  = (idx < L) ? idx : (L - 1);
                cp_async4z(wdst + (((cs + 1) & 1) << 7), wlane + ic, ssz);
                cp_commit();
                cp_wait1();               // chunk cs landed
            } else {
                cp_wait0();
            }
            __syncwarp();
            const float4* wb = (const float4*)(wsw + ((cs & 1) << 5));
            const float4* xc = xs4 + (size_t)(b + (cs << 3)) * 64 + lane;
            // straight-line: zero weights cancel out-of-window ksteps
#pragma unroll
            for (int u = 0; u < 8; u++) {
                float4 w4 = wb[u];        // broadcast: 4 streams' weights
                float4 xA = xc[u * 64];       // rows 4*lane..
                float4 xB = xc[u * 64 + 32];  // rows 128+4*lane..
                acc[0][0] += w4.x * xA.x; acc[0][1] += w4.x * xA.y;
                acc[0][2] += w4.x * xA.z; acc[0][3] += w4.x * xA.w;
                acc[0][4] += w4.x * xB.x; acc[0][5] += w4.x * xB.y;
                acc[0][6] += w4.x * xB.z; acc[0][7] += w4.x * xB.w;
                acc[1][0] += w4.y * xA.x; acc[1][1] += w4.y * xA.y;
                acc[1][2] += w4.y * xA.z; acc[1][3] += w4.y * xA.w;
                acc[1][4] += w4.y * xB.x; acc[1][5] += w4.y * xB.y;
                acc[1][6] += w4.y * xB.z; acc[1][7] += w4.y * xB.w;
                acc[2][0] += w4.z * xA.x; acc[2][1] += w4.z * xA.y;
                acc[2][2] += w4.z * xA.z; acc[2][3] += w4.z * xA.w;
                acc[2][4] += w4.z * xB.x; acc[2][5] += w4.z * xB.y;
                acc[2][6] += w4.z * xB.z; acc[2][7] += w4.z * xB.w;
                acc[3][0] += w4.w * xA.x; acc[3][1] += w4.w * xA.y;
                acc[3][2] += w4.w * xA.z; acc[3][3] += w4.w * xA.w;
                acc[3][4] += w4.w * xB.x; acc[3][5] += w4.w * xB.y;
                acc[3][6] += w4.w * xB.z; acc[3][7] += w4.w * xB.w;
            }
            __syncwarp();                 // consume done before buffer reuse
        }

        // epilogue: ov += (x_a * x_b) * s_ab  (linearity allows partial runs)
        {
            float4 xb0 = xs4[(size_t)b * 64 + lane];
            float4 xb1 = xs4[(size_t)b * 64 + lane + 32];
#pragma unroll
            for (int j = 0; j < 4; j++) {
                if (j < na) {
                    const float4* xap = xs4 + (size_t)(a0 + j) * 64 + lane;
                    float4 xa0 = xap[0];
                    float4 xa1 = xap[32];
                    ov[0] += xa0.x * xb0.x * acc[j][0];
                    ov[1] += xa0.y * xb0.y * acc[j][1];
                    ov[2] += xa0.z * xb0.z * acc[j][2];
                    ov[3] += xa0.w * xb0.w * acc[j][3];
                    ov[4] += xa1.x * xb1.x * acc[j][4];
                    ov[5] += xa1.y * xb1.y * acc[j][5];
                    ov[6] += xa1.z * xb1.z * acc[j][6];
                    ov[7] += xa1.w * xb1.w * acc[j][7];
                }
            }
        }

        pos += kend - k0;
        if (kend == L) {
            k0 = 0;
            o++;
            if ((o << 2) > b) { o = 0; b++; }
        } else {
            k0 = kend;
        }
    }

    // ---- per-warp partials -> smem, block combine -> global (transposed) ----
    {
        float4* ob = (float4*)(obuf + warp * NROW);
        ob[lane]      = make_float4(ov[0], ov[1], ov[2], ov[3]);  // rows 4l..
        ob[lane + 32] = make_float4(ov[4], ov[5], ov[6], ov[7]);  // rows 128+4l..
    }
    __syncthreads();
    if (tid < NROW) {
        float ssum = 0.0f;
#pragma unroll
        for (int k = 0; k < WPB; k++) ssum += obuf[k * NROW + tid];
        g_partial[tid * NBLK + blockIdx.x] = ssum;   // transposed store
    }
}

// One block per row; contiguous 148-float read; shuffle + smem tree reduce.
__global__ void __launch_bounds__(128, 8)
honu_reduce(float* __restrict__ out) {
    __shared__ float wsum[4];
    int r = blockIdx.x;
    int t = threadIdx.x;
    const float* p = g_partial + r * NBLK;

    float v = (t < NBLK) ? p[t] : 0.0f;
    if (t + 128 < NBLK) v += p[t + 128];

#pragma unroll
    for (int d = 16; d > 0; d >>= 1)
        v += __shfl_down_sync(0xFFFFFFFFu, v, d);
    if ((t & 31) == 0) wsum[t >> 5] = v;
    __syncthreads();
    if (t == 0)
        out[r] = (wsum[0] + wsum[1]) + (wsum[2] + wsum[3]);
}

extern "C" void kernel_launch(void* const* d_in, const int* in_sizes, int n_in,
                              void* d_out, int out_size) {
    (void)in_sizes; (void)n_in; (void)out_size;
    const float* x = (const float*)d_in[0];
    const float* w = (const float*)d_in[1];
    // d_in[2] (comb_idx) intentionally unused: lexicographic rank is closed-form.

    size_t smem_bytes =
        (size_t)(XROWS * NROW + WPB * NROW + WPB * 64) * sizeof(float);  // 159,744 B
    cudaFuncSetAttribute(honu_main, cudaFuncAttributeMaxDynamicSharedMemorySize,
                         (int)smem_bytes);
    honu_main<<<NBLK, 512, smem_bytes>>>(x, w);
    honu_reduce<<<NROW, 128>>>((float*)d_out);
}